// round 1
// baseline (speedup 1.0000x reference)
#include <cuda_runtime.h>
#include <math.h>

// Problem constants (from setup_inputs; p_sample=100 fixed)
#define Bn   512
#define Kd   256
#define KH   128
#define Gg   384     // 3*KH
#define Tt   101     // p_sample+1
#define Ff   16
#define MGX  (Bn*Tt) // 51712 = 808*64 exactly

// ---------------- scratch (device globals: allocation-free) ----------------
__device__ float g_gx[MGX * Gg];          // [m=b*101+t][g]
__device__ float g_WihT[Kd * Gg];         // [k][g]
__device__ float g_WkT[Ff * KH * Kd];     // [f][h][k]
__device__ float g_ctT[KH * Bn];          // [h][b]
__device__ float g_predT[Ff * Kd * Bn];   // [f][k][c]
__device__ float g_encT[Ff * Kd * Bn];    // [f][k][b]
__device__ float g_totals[Ff * Bn * Bn];  // [f][b][c]
__device__ float g_lse15[Bn];
__device__ float g_diag[Ff * Bn];
__device__ int   g_ok[Bn];

// ---------------- passthrough copy ----------------
__global__ void k_copy(const float2* __restrict__ a, const float2* __restrict__ b,
                       float2* __restrict__ dst, long n2) {
    long i = blockIdx.x * (long)blockDim.x + threadIdx.x;
    long stride = (long)gridDim.x * blockDim.x;
    for (; i < n2; i += stride) {
        dst[i]      = a[i];
        dst[i + n2] = b[i];
    }
}

// ---------------- weight transposes (tiny) ----------------
__global__ void k_transpose_wih(const float* __restrict__ W) {
    int idx = blockIdx.x * 256 + threadIdx.x;           // 384*256
    if (idx < Gg * Kd) {
        int g = idx / Kd, k = idx % Kd;
        g_WihT[k * Gg + g] = W[idx];
    }
}
__global__ void k_transpose_wk(const float* __restrict__ W) {
    int idx = blockIdx.x * 256 + threadIdx.x;           // 16*256*128
    if (idx < Ff * Kd * KH) {
        int f = idx >> 15, r = idx & 32767, k = r >> 7, h = r & 127;
        g_WkT[f * (KH * Kd) + h * Kd + k] = W[idx];
    }
}

// ---------------- gx = seq @ W_ih^T + b_ih  (M=51712, N=384, K=256) --------
__global__ __launch_bounds__(256) void k_gx(const float* __restrict__ z,
                                            const float* __restrict__ bih) {
    __shared__ float As[32][64];
    __shared__ float Bs[32][128];
    int tid = threadIdx.x;
    int m0 = blockIdx.x * 64, n0 = blockIdx.y * 128;

    int mA = m0 + (tid & 63);
    int kA0 = tid >> 6;                       // 0..3
    int bq = mA / Tt, tq = mA - bq * Tt;      // fixed per thread
    const float* aptr = z + (size_t)bq * (Kd * 256) + tq;

    int nB = n0 + (tid & 127);
    int kB0 = tid >> 7;                       // 0..1
    int tx = tid & 31, ty = tid >> 5;

    float acc[8][4] = {};
    for (int kt = 0; kt < Kd; kt += 32) {
#pragma unroll
        for (int i = 0; i < 8; i++) {
            int kl = kA0 + 4 * i;
            As[kl][tid & 63] = aptr[(size_t)(kt + kl) * 256];
        }
#pragma unroll
        for (int i = 0; i < 16; i++) {
            int kl = kB0 + 2 * i;
            Bs[kl][tid & 127] = g_WihT[(kt + kl) * Gg + nB];
        }
        __syncthreads();
#pragma unroll
        for (int k = 0; k < 32; k++) {
            float4 b4 = *(const float4*)&Bs[k][tx * 4];
            float4 a0 = *(const float4*)&As[k][ty * 8];
            float4 a1 = *(const float4*)&As[k][ty * 8 + 4];
            float av[8] = {a0.x, a0.y, a0.z, a0.w, a1.x, a1.y, a1.z, a1.w};
            float bv[4] = {b4.x, b4.y, b4.z, b4.w};
#pragma unroll
            for (int i = 0; i < 8; i++)
#pragma unroll
                for (int j = 0; j < 4; j++) acc[i][j] += av[i] * bv[j];
        }
        __syncthreads();
    }
    float4 bias = *(const float4*)&bih[n0 + tx * 4];
#pragma unroll
    for (int i = 0; i < 8; i++) {
        int m = m0 + ty * 8 + i;
        float4 v = {acc[i][0] + bias.x, acc[i][1] + bias.y,
                    acc[i][2] + bias.z, acc[i][3] + bias.w};
        *(float4*)&g_gx[(size_t)m * Gg + n0 + tx * 4] = v;
    }
}

// ---------------- persistent GRU: 128 CTAs x 4 rows x 101 steps ------------
__global__ __launch_bounds__(768, 1) void k_gru(const float* __restrict__ h0,
                                                const float* __restrict__ Whh,
                                                const float* __restrict__ bhh) {
    __shared__ __align__(16) float h_sm[4][128];
    __shared__ float gh_sm[4][Gg];
    __shared__ float bh_sm[Gg];
    int tid = threadIdx.x;
    int b0 = blockIdx.x * 4;
    int g = tid >> 1, half = tid & 1;

    // cache this thread's 64 W_hh weights in registers (persistent across steps)
    float4 w[16];
    const float4* wp = (const float4*)(Whh + g * KH + half * 64);
#pragma unroll
    for (int i = 0; i < 16; i++) w[i] = wp[i];

    if (tid < Gg) bh_sm[tid] = bhh[tid];
    int r2 = tid >> 7, j2 = tid & 127;         // valid for tid<512
    if (tid < 512) h_sm[r2][j2] = h0[(b0 + r2) * KH + j2];
    __syncthreads();

    size_t gxbase = (size_t)(b0 + r2) * Tt * Gg;
    for (int t = 0; t < Tt; t++) {
        float xr = 0.f, xz = 0.f, xn = 0.f;
        if (tid < 512) {
            const float* gp = g_gx + gxbase + (size_t)t * Gg;
            xr = gp[j2]; xz = gp[128 + j2]; xn = gp[256 + j2];
        }
        // phase 1: gh[r][g] = h[r,:] . Whh[g,:]
#pragma unroll
        for (int r = 0; r < 4; r++) {
            float acc = 0.f;
            const float4* hp = (const float4*)&h_sm[r][half * 64];
#pragma unroll
            for (int i = 0; i < 16; i++) {
                float4 hv = hp[i];
                acc += w[i].x * hv.x + w[i].y * hv.y + w[i].z * hv.z + w[i].w * hv.w;
            }
            acc += __shfl_xor_sync(0xffffffffu, acc, 1);
            if (half == 0) gh_sm[r][g] = acc;
        }
        __syncthreads();
        // phase 2: gates + state update
        if (tid < 512) {
            float hr = gh_sm[r2][j2]       + bh_sm[j2];
            float hz = gh_sm[r2][128 + j2] + bh_sm[128 + j2];
            float hn = gh_sm[r2][256 + j2] + bh_sm[256 + j2];
            float rr = 1.f / (1.f + expf(-(xr + hr)));
            float zz = 1.f / (1.f + expf(-(xz + hz)));
            float nn = tanhf(xn + rr * hn);
            float hp = h_sm[r2][j2];
            h_sm[r2][j2] = (1.f - zz) * nn + zz * hp;
        }
        __syncthreads();
    }
    if (tid < 512) g_ctT[j2 * Bn + (b0 + r2)] = h_sm[r2][j2];
}

// ---------------- encoded gather: encT[f][k][b] = z[b][k][101+f] -----------
__global__ void k_enc(const float* __restrict__ z) {
    int idx = blockIdx.x * 256 + threadIdx.x;    // 16*256*512
    if (idx < Ff * Kd * Bn) {
        int b = idx & 511, k = (idx >> 9) & 255, f = idx >> 17;
        g_encT[idx] = z[(size_t)b * (Kd * 256) + k * 256 + (Tt + f)];
    }
}

// ------------- generic batched GEMM: C[m][n] = sum_k A[k][m]*B[k][n] -------
__global__ __launch_bounds__(256) void k_gemm(const float* __restrict__ A,
                                              const float* __restrict__ Bm,
                                              float* __restrict__ C,
                                              int lda, int ldb, int ldc, int KK,
                                              long sA, long sB, long sC,
                                              const float* __restrict__ rowBias, int sBias) {
    __shared__ float As[32][64];
    __shared__ float Bs[32][128];
    int f = blockIdx.z;
    A += (long)f * sA; Bm += (long)f * sB; C += (long)f * sC;
    int tid = threadIdx.x;
    int m0 = blockIdx.y * 64, n0 = blockIdx.x * 128;
    int mA = m0 + (tid & 63), kA0 = tid >> 6;
    int nB = n0 + (tid & 127), kB0 = tid >> 7;
    int tx = tid & 31, ty = tid >> 5;
    float acc[8][4] = {};
    for (int kt = 0; kt < KK; kt += 32) {
#pragma unroll
        for (int i = 0; i < 8; i++) { int kl = kA0 + 4 * i; As[kl][tid & 63] = A[(long)(kt + kl) * lda + mA]; }
#pragma unroll
        for (int i = 0; i < 16; i++) { int kl = kB0 + 2 * i; Bs[kl][tid & 127] = Bm[(long)(kt + kl) * ldb + nB]; }
        __syncthreads();
#pragma unroll
        for (int k = 0; k < 32; k++) {
            float4 b4 = *(const float4*)&Bs[k][tx * 4];
            float4 a0 = *(const float4*)&As[k][ty * 8];
            float4 a1 = *(const float4*)&As[k][ty * 8 + 4];
            float av[8] = {a0.x, a0.y, a0.z, a0.w, a1.x, a1.y, a1.z, a1.w};
            float bv[4] = {b4.x, b4.y, b4.z, b4.w};
#pragma unroll
            for (int i = 0; i < 8; i++)
#pragma unroll
                for (int j = 0; j < 4; j++) acc[i][j] += av[i] * bv[j];
        }
        __syncthreads();
    }
#pragma unroll
    for (int i = 0; i < 8; i++) {
        int m = m0 + ty * 8 + i;
        float bias = rowBias ? rowBias[(long)f * sBias + m] : 0.f;
        float4 v = {acc[i][0] + bias, acc[i][1] + bias, acc[i][2] + bias, acc[i][3] + bias};
        *(float4*)&C[(long)m * ldc + n0 + tx * 4] = v;
    }
}

// ---------------- per-row logsumexp + diagonal of log_softmax --------------
__global__ void k_lse() {
    int row = blockIdx.x;                       // f*512 + b
    const float* p = g_totals + (size_t)row * Bn;
    int tid = threadIdx.x;                      // 128
    __shared__ float sm[128];
    float mx = -1e30f;
    for (int c = tid; c < Bn; c += 128) mx = fmaxf(mx, p[c]);
    sm[tid] = mx; __syncthreads();
    for (int s = 64; s; s >>= 1) { if (tid < s) sm[tid] = fmaxf(sm[tid], sm[tid + s]); __syncthreads(); }
    mx = sm[0]; __syncthreads();
    float sum = 0.f;
    for (int c = tid; c < Bn; c += 128) sum += expf(p[c] - mx);
    sm[tid] = sum; __syncthreads();
    for (int s = 64; s; s >>= 1) { if (tid < s) sm[tid] += sm[tid + s]; __syncthreads(); }
    if (tid == 0) {
        float lse = mx + logf(sm[0]);
        int b = row & 511, f = row >> 9;
        g_diag[row] = p[b] - lse;
        if (f == Ff - 1) g_lse15[b] = lse;
    }
}

// ---------------- accuracy: argmax over b of softmax column ----------------
__global__ void k_acc() {
    int c = blockIdx.x;
    const float* p = g_totals + (size_t)(Ff - 1) * Bn * Bn;
    int tid = threadIdx.x;                      // 128
    float best = -1e30f; int bi = 1 << 30;
    for (int b = tid; b < Bn; b += 128) {
        float v = p[(size_t)b * Bn + c] - g_lse15[b];
        if (v > best) { best = v; bi = b; }
    }
    __shared__ float sv[128]; __shared__ int si[128];
    sv[tid] = best; si[tid] = bi; __syncthreads();
    for (int s = 64; s; s >>= 1) {
        if (tid < s) {
            float v2 = sv[tid + s]; int i2 = si[tid + s];
            if (v2 > sv[tid] || (v2 == sv[tid] && i2 < si[tid])) { sv[tid] = v2; si[tid] = i2; }
        }
        __syncthreads();
    }
    if (tid == 0) g_ok[c] = (si[0] == c) ? 1 : 0;
}

// ---------------- deterministic final reduction -----------------------------
__global__ void k_final(float* __restrict__ out) {
    __shared__ float s[256]; __shared__ int si[256];
    int tid = threadIdx.x;
    float sum = 0.f;
    for (int i = tid; i < Ff * Bn; i += 256) sum += g_diag[i];
    int cnt = 0;
    for (int i = tid; i < Bn; i += 256) cnt += g_ok[i];
    s[tid] = sum; si[tid] = cnt; __syncthreads();
    for (int st = 128; st; st >>= 1) {
        if (tid < st) { s[tid] += s[tid + st]; si[tid] += si[tid + st]; }
        __syncthreads();
    }
    if (tid == 0) {
        out[0] = (float)si[0] / (float)Bn;               // accuracy
        out[1] = -s[0] / (float)(Ff * Bn);               // nce
    }
}

// ---------------- host ----------------
extern "C" void kernel_launch(void* const* d_in, const int* in_sizes, int n_in,
                              void* d_out, int out_size) {
    const float* zqst   = (const float*)d_in[0];
    const float* zex    = (const float*)d_in[1];
    const float* zqx    = (const float*)d_in[2];
    const float* hidden = (const float*)d_in[3];
    // d_in[4] = W_ih, d_in[5] = W_hh, d_in[6] = b_ih, d_in[7] = b_hh
    const float* Wih = (const float*)d_in[4];
    const float* Whh = (const float*)d_in[5];
    const float* bih = (const float*)d_in[6];
    const float* bhh = (const float*)d_in[7];
    const float* Wkw = (const float*)d_in[8];
    const float* Wkb = (const float*)d_in[9];
    float* out = (float*)d_out;

    float *p_wkT, *p_ctT, *p_predT, *p_encT, *p_totals;
    cudaGetSymbolAddress((void**)&p_wkT,    g_WkT);
    cudaGetSymbolAddress((void**)&p_ctT,    g_ctT);
    cudaGetSymbolAddress((void**)&p_predT,  g_predT);
    cudaGetSymbolAddress((void**)&p_encT,   g_encT);
    cudaGetSymbolAddress((void**)&p_totals, g_totals);

    k_transpose_wih<<<(Gg * Kd + 255) / 256, 256>>>(Wih);
    k_transpose_wk<<<(Ff * Kd * KH + 255) / 256, 256>>>(Wkw);

    k_gx<<<dim3(MGX / 64, Gg / 128), 256>>>(zqst, bih);
    k_gru<<<Bn / 4, 768>>>(hidden, Whh, bhh);
    k_enc<<<(Ff * Kd * Bn + 255) / 256, 256>>>(zqst);

    // predT[f][k][c] = sum_h WkT[f][h][k] * ctT[h][c] + Wk_b[f][k]
    k_gemm<<<dim3(Bn / 128, Kd / 64, Ff), 256>>>(p_wkT, p_ctT, p_predT,
        Kd, Bn, Bn, KH, (long)KH * Kd, 0L, (long)Kd * Bn, Wkb, Kd);
    // totals[f][b][c] = sum_k encT[f][k][b] * predT[f][k][c]
    k_gemm<<<dim3(Bn / 128, Bn / 64, Ff), 256>>>(p_encT, p_predT, p_totals,
        Bn, Bn, Bn, Kd, (long)Kd * Bn, (long)Kd * Bn, (long)Bn * Bn, nullptr, 0);

    k_lse<<<Ff * Bn, 128>>>();
    k_acc<<<Bn, 128>>>();
    k_final<<<1, 256>>>(out);

    // passthrough: out[2:] = [z_e_x, z_q_x]
    k_copy<<<8192, 256>>>((const float2*)zex, (const float2*)zqx,
                          (float2*)(out + 2), (long)(Bn * Kd * 256) / 2);
}

// round 2
// speedup vs baseline: 1.0424x; 1.0424x over previous
#include <cuda_runtime.h>
#include <math.h>

// Problem constants (from setup_inputs; p_sample=100 fixed)
#define Bn   512
#define Kd   256
#define KH   128
#define Gg   384     // 3*KH
#define Tt   101     // p_sample+1
#define Ff   16
#define MGX  (Bn*Tt) // 51712 = 808*64 exactly
#define GXB  (MGX/64)  // 808 gemm blocks along m
#define CPB  256       // copy blocks fused into k_gx

// ---------------- packed fp32x2 helpers (sm_103a FFMA2) ----------------
typedef unsigned long long ull;
__device__ __forceinline__ ull ff2(ull a, ull b, ull c) {
    ull d;
    asm("fma.rn.f32x2 %0, %1, %2, %3;" : "=l"(d) : "l"(a), "l"(b), "l"(c));
    return d;
}
__device__ __forceinline__ ull dup2(float x) {
    ull r; asm("mov.b64 %0, {%1, %1};" : "=l"(r) : "f"(x)); return r;
}
__device__ __forceinline__ float2 unpk2(ull v) {
    float2 r; asm("mov.b64 {%0, %1}, %2;" : "=f"(r.x), "=f"(r.y) : "l"(v)); return r;
}

// ---------------- scratch (device globals: allocation-free) ----------------
__device__ float g_gx[MGX * Gg];          // [m=b*101+t][g]
__device__ float g_WihT[Kd * Gg];         // [k][g]
__device__ float g_WkT[Ff * KH * Kd];     // [f][h][k]
__device__ float g_ctT[KH * Bn];          // [h][b]
__device__ float g_predT[Ff * Kd * Bn];   // [f][k][c]
__device__ float g_encT[Ff * Kd * Bn];    // [f][k][b]
__device__ float g_totals[Ff * Bn * Bn];  // [f][b][c]
__device__ float g_lse15[Bn];
__device__ float g_diag[Ff * Bn];
__device__ int   g_ok[Bn];

// ---------------- weight transposes (tiny) ----------------
__global__ void k_transpose_wih(const float* __restrict__ W) {
    int idx = blockIdx.x * 256 + threadIdx.x;           // 384*256
    if (idx < Gg * Kd) {
        int g = idx / Kd, k = idx % Kd;
        g_WihT[k * Gg + g] = W[idx];
    }
}
__global__ void k_transpose_wk(const float* __restrict__ W) {
    int idx = blockIdx.x * 256 + threadIdx.x;           // 16*256*128
    if (idx < Ff * Kd * KH) {
        int f = idx >> 15, r = idx & 32767, k = r >> 7, h = r & 127;
        g_WkT[f * (KH * Kd) + h * Kd + k] = W[idx];
    }
}

// ---------------- encoded gather: encT[f][k][b] = z[b][k][101+f] -----------
__global__ void k_enc(const float* __restrict__ z) {
    int idx = blockIdx.x * 256 + threadIdx.x;    // 16*256*512
    if (idx < Ff * Kd * Bn) {
        int b = idx & 511, k = (idx >> 9) & 255, f = idx >> 17;
        g_encT[idx] = z[(size_t)b * (Kd * 256) + k * 256 + (Tt + f)];
    }
}

// ---------------- gx = seq @ W_ih^T + b_ih  + fused passthrough copy -------
// GEMM blocks: blockIdx.x < GXB (m tiles of 64), blockIdx.y = n tile of 128.
// Copy blocks: blockIdx.x >= GXB && blockIdx.y == 0 : grid-stride copy.
__global__ __launch_bounds__(256) void k_gx(const float* __restrict__ z,
                                            const float* __restrict__ bih,
                                            const float2* __restrict__ cpA,
                                            const float2* __restrict__ cpB,
                                            float2* __restrict__ cpDst) {
    if (blockIdx.x >= GXB) {
        if (blockIdx.y != 0) return;
        // passthrough copy: 2 * 33.55M floats
        const long n2 = (long)Bn * Kd * 256 / 2;
        long i = (blockIdx.x - GXB) * 256L + threadIdx.x;
        const long stride = (long)CPB * 256;
        for (; i < n2; i += stride) {
            cpDst[i]      = cpA[i];
            cpDst[i + n2] = cpB[i];
        }
        return;
    }

    __shared__ float As[32][64];
    __shared__ float Bs[32][128];
    int tid = threadIdx.x;
    int m0 = blockIdx.x * 64, n0 = blockIdx.y * 128;

    int mA = m0 + (tid & 63);
    int kA0 = tid >> 6;                       // 0..3
    int bq = mA / Tt, tq = mA - bq * Tt;      // fixed per thread
    const float* aptr = z + (size_t)bq * (Kd * 256) + tq;

    int nB = n0 + (tid & 127);
    int kB0 = tid >> 7;                       // 0..1
    int tx = tid & 31, ty = tid >> 5;

    ull acc[4][4];                             // [m-pair][n], packed along m
#pragma unroll
    for (int i = 0; i < 4; i++)
#pragma unroll
        for (int j = 0; j < 4; j++) acc[i][j] = 0ULL;

    for (int kt = 0; kt < Kd; kt += 32) {
#pragma unroll
        for (int i = 0; i < 8; i++) {
            int kl = kA0 + 4 * i;
            As[kl][tid & 63] = aptr[(size_t)(kt + kl) * 256];
        }
#pragma unroll
        for (int i = 0; i < 16; i++) {
            int kl = kB0 + 2 * i;
            Bs[kl][tid & 127] = g_WihT[(kt + kl) * Gg + nB];
        }
        __syncthreads();
#pragma unroll
        for (int k = 0; k < 32; k++) {
            ulonglong2 a0 = *(const ulonglong2*)&As[k][ty * 8];
            ulonglong2 a1 = *(const ulonglong2*)&As[k][ty * 8 + 4];
            float4 b4 = *(const float4*)&Bs[k][tx * 4];
            ull bb[4] = {dup2(b4.x), dup2(b4.y), dup2(b4.z), dup2(b4.w)};
            ull am[4] = {a0.x, a0.y, a1.x, a1.y};
#pragma unroll
            for (int i = 0; i < 4; i++)
#pragma unroll
                for (int j = 0; j < 4; j++) acc[i][j] = ff2(am[i], bb[j], acc[i][j]);
        }
        __syncthreads();
    }
    float4 bias = *(const float4*)&bih[n0 + tx * 4];
#pragma unroll
    for (int i = 0; i < 4; i++) {
        float2 c0 = unpk2(acc[i][0]), c1 = unpk2(acc[i][1]);
        float2 c2 = unpk2(acc[i][2]), c3 = unpk2(acc[i][3]);
        int mlo = m0 + ty * 8 + 2 * i;
        float4 vlo = {c0.x + bias.x, c1.x + bias.y, c2.x + bias.z, c3.x + bias.w};
        float4 vhi = {c0.y + bias.x, c1.y + bias.y, c2.y + bias.z, c3.y + bias.w};
        *(float4*)&g_gx[(size_t)mlo * Gg + n0 + tx * 4] = vlo;
        *(float4*)&g_gx[(size_t)(mlo + 1) * Gg + n0 + tx * 4] = vhi;
    }
}

// ---------------- persistent GRU: 128 CTAs x 4 rows x 101 steps ------------
__global__ __launch_bounds__(768, 1) void k_gru(const float* __restrict__ h0,
                                                const float* __restrict__ Whh,
                                                const float* __restrict__ bhh) {
    __shared__ __align__(16) float h_sm[4][128];
    __shared__ float gh_sm[4][Gg];
    __shared__ float bh_sm[Gg];
    int tid = threadIdx.x;
    int b0 = blockIdx.x * 4;
    int g = tid >> 1, half = tid & 1;

    // cache this thread's 64 W_hh weights as 32 packed fp32 pairs
    ull w2[32];
    const ulonglong2* wp = (const ulonglong2*)(Whh + g * KH + half * 64);
#pragma unroll
    for (int i = 0; i < 16; i++) {
        ulonglong2 v = wp[i];
        w2[2 * i] = v.x; w2[2 * i + 1] = v.y;
    }

    if (tid < Gg) bh_sm[tid] = bhh[tid];
    int r2 = tid >> 7, j2 = tid & 127;         // valid for tid<512
    if (tid < 512) h_sm[r2][j2] = h0[(b0 + r2) * KH + j2];
    __syncthreads();

    size_t gxbase = (size_t)(b0 + r2) * Tt * Gg;
    for (int t = 0; t < Tt; t++) {
        float xr = 0.f, xz = 0.f, xn = 0.f;
        if (tid < 512) {
            const float* gp = g_gx + gxbase + (size_t)t * Gg;
            xr = gp[j2]; xz = gp[128 + j2]; xn = gp[256 + j2];
        }
        // phase 1: gh[r][g] = h[r,:] . Whh[g,:]  via packed FFMA2
#pragma unroll
        for (int r = 0; r < 4; r++) {
            ull accA = 0ULL, accB = 0ULL;
            const ulonglong2* hp = (const ulonglong2*)&h_sm[r][half * 64];
#pragma unroll
            for (int i = 0; i < 16; i++) {
                ulonglong2 hv = hp[i];
                accA = ff2(w2[2 * i], hv.x, accA);
                accB = ff2(w2[2 * i + 1], hv.y, accB);
            }
            float2 sa = unpk2(accA), sb = unpk2(accB);
            float acc = (sa.x + sa.y) + (sb.x + sb.y);
            acc += __shfl_xor_sync(0xffffffffu, acc, 1);
            if (half == 0) gh_sm[r][g] = acc;
        }
        __syncthreads();
        // phase 2: gates + state update
        if (tid < 512) {
            float hr = gh_sm[r2][j2]       + bh_sm[j2];
            float hz = gh_sm[r2][128 + j2] + bh_sm[128 + j2];
            float hn = gh_sm[r2][256 + j2] + bh_sm[256 + j2];
            float rr = 1.f / (1.f + __expf(-(xr + hr)));
            float zz = 1.f / (1.f + __expf(-(xz + hz)));
            float nn = tanhf(xn + rr * hn);
            float hp = h_sm[r2][j2];
            h_sm[r2][j2] = (1.f - zz) * nn + zz * hp;
        }
        __syncthreads();
    }
    if (tid < 512) g_ctT[j2 * Bn + (b0 + r2)] = h_sm[r2][j2];
}

// ------------- generic batched GEMM: C[m][n] = sum_k A[k][m]*B[k][n] -------
__global__ __launch_bounds__(256) void k_gemm(const float* __restrict__ A,
                                              const float* __restrict__ Bm,
                                              float* __restrict__ C,
                                              int lda, int ldb, int ldc, int KK,
                                              long sA, long sB, long sC,
                                              const float* __restrict__ rowBias, int sBias) {
    __shared__ float As[32][64];
    __shared__ float Bs[32][128];
    int f = blockIdx.z;
    A += (long)f * sA; Bm += (long)f * sB; C += (long)f * sC;
    int tid = threadIdx.x;
    int m0 = blockIdx.y * 64, n0 = blockIdx.x * 128;
    int mA = m0 + (tid & 63), kA0 = tid >> 6;
    int nB = n0 + (tid & 127), kB0 = tid >> 7;
    int tx = tid & 31, ty = tid >> 5;
    ull acc[4][4];
#pragma unroll
    for (int i = 0; i < 4; i++)
#pragma unroll
        for (int j = 0; j < 4; j++) acc[i][j] = 0ULL;

    for (int kt = 0; kt < KK; kt += 32) {
#pragma unroll
        for (int i = 0; i < 8; i++) { int kl = kA0 + 4 * i; As[kl][tid & 63] = A[(long)(kt + kl) * lda + mA]; }
#pragma unroll
        for (int i = 0; i < 16; i++) { int kl = kB0 + 2 * i; Bs[kl][tid & 127] = Bm[(long)(kt + kl) * ldb + nB]; }
        __syncthreads();
#pragma unroll
        for (int k = 0; k < 32; k++) {
            ulonglong2 a0 = *(const ulonglong2*)&As[k][ty * 8];
            ulonglong2 a1 = *(const ulonglong2*)&As[k][ty * 8 + 4];
            float4 b4 = *(const float4*)&Bs[k][tx * 4];
            ull bb[4] = {dup2(b4.x), dup2(b4.y), dup2(b4.z), dup2(b4.w)};
            ull am[4] = {a0.x, a0.y, a1.x, a1.y};
#pragma unroll
            for (int i = 0; i < 4; i++)
#pragma unroll
                for (int j = 0; j < 4; j++) acc[i][j] = ff2(am[i], bb[j], acc[i][j]);
        }
        __syncthreads();
    }
#pragma unroll
    for (int i = 0; i < 4; i++) {
        int mlo = m0 + ty * 8 + 2 * i;
        float blo = rowBias ? rowBias[(long)f * sBias + mlo] : 0.f;
        float bhi = rowBias ? rowBias[(long)f * sBias + mlo + 1] : 0.f;
        float2 c0 = unpk2(acc[i][0]), c1 = unpk2(acc[i][1]);
        float2 c2 = unpk2(acc[i][2]), c3 = unpk2(acc[i][3]);
        float4 vlo = {c0.x + blo, c1.x + blo, c2.x + blo, c3.x + blo};
        float4 vhi = {c0.y + bhi, c1.y + bhi, c2.y + bhi, c3.y + bhi};
        *(float4*)&C[(long)mlo * ldc + n0 + tx * 4] = vlo;
        *(float4*)&C[(long)(mlo + 1) * ldc + n0 + tx * 4] = vhi;
    }
}

// ---------------- per-row logsumexp + diagonal of log_softmax --------------
__global__ void k_lse() {
    int row = blockIdx.x;                       // f*512 + b
    const float* p = g_totals + (size_t)row * Bn;
    int tid = threadIdx.x;                      // 128
    __shared__ float sm[128];
    float mx = -1e30f;
    for (int c = tid; c < Bn; c += 128) mx = fmaxf(mx, p[c]);
    sm[tid] = mx; __syncthreads();
    for (int s = 64; s; s >>= 1) { if (tid < s) sm[tid] = fmaxf(sm[tid], sm[tid + s]); __syncthreads(); }
    mx = sm[0]; __syncthreads();
    float sum = 0.f;
    for (int c = tid; c < Bn; c += 128) sum += expf(p[c] - mx);
    sm[tid] = sum; __syncthreads();
    for (int s = 64; s; s >>= 1) { if (tid < s) sm[tid] += sm[tid + s]; __syncthreads(); }
    if (tid == 0) {
        float lse = mx + logf(sm[0]);
        int b = row & 511, f = row >> 9;
        g_diag[row] = p[b] - lse;
        if (f == Ff - 1) g_lse15[b] = lse;
    }
}

// ---------------- accuracy: argmax over b of softmax column ----------------
__global__ void k_acc() {
    int c = blockIdx.x;
    const float* p = g_totals + (size_t)(Ff - 1) * Bn * Bn;
    int tid = threadIdx.x;                      // 128
    float best = -1e30f; int bi = 1 << 30;
    for (int b = tid; b < Bn; b += 128) {
        float v = p[(size_t)b * Bn + c] - g_lse15[b];
        if (v > best) { best = v; bi = b; }
    }
    __shared__ float sv[128]; __shared__ int si[128];
    sv[tid] = best; si[tid] = bi; __syncthreads();
    for (int s = 64; s; s >>= 1) {
        if (tid < s) {
            float v2 = sv[tid + s]; int i2 = si[tid + s];
            if (v2 > sv[tid] || (v2 == sv[tid] && i2 < si[tid])) { sv[tid] = v2; si[tid] = i2; }
        }
        __syncthreads();
    }
    if (tid == 0) g_ok[c] = (si[0] == c) ? 1 : 0;
}

// ---------------- deterministic final reduction -----------------------------
__global__ void k_final(float* __restrict__ out) {
    __shared__ float s[256]; __shared__ int si[256];
    int tid = threadIdx.x;
    float sum = 0.f;
    for (int i = tid; i < Ff * Bn; i += 256) sum += g_diag[i];
    int cnt = 0;
    for (int i = tid; i < Bn; i += 256) cnt += g_ok[i];
    s[tid] = sum; si[tid] = cnt; __syncthreads();
    for (int st = 128; st; st >>= 1) {
        if (tid < st) { s[tid] += s[tid + st]; si[tid] += si[tid + st]; }
        __syncthreads();
    }
    if (tid == 0) {
        out[0] = (float)si[0] / (float)Bn;               // accuracy
        out[1] = -s[0] / (float)(Ff * Bn);               // nce
    }
}

// ---------------- host ----------------
extern "C" void kernel_launch(void* const* d_in, const int* in_sizes, int n_in,
                              void* d_out, int out_size) {
    const float* zqst   = (const float*)d_in[0];
    const float* zex    = (const float*)d_in[1];
    const float* zqx    = (const float*)d_in[2];
    const float* hidden = (const float*)d_in[3];
    const float* Wih = (const float*)d_in[4];
    const float* Whh = (const float*)d_in[5];
    const float* bih = (const float*)d_in[6];
    const float* bhh = (const float*)d_in[7];
    const float* Wkw = (const float*)d_in[8];
    const float* Wkb = (const float*)d_in[9];
    float* out = (float*)d_out;

    float *p_wkT, *p_ctT, *p_predT, *p_encT, *p_totals;
    cudaGetSymbolAddress((void**)&p_wkT,    g_WkT);
    cudaGetSymbolAddress((void**)&p_ctT,    g_ctT);
    cudaGetSymbolAddress((void**)&p_predT,  g_predT);
    cudaGetSymbolAddress((void**)&p_encT,   g_encT);
    cudaGetSymbolAddress((void**)&p_totals, g_totals);

    k_transpose_wih<<<(Gg * Kd + 255) / 256, 256>>>(Wih);
    k_transpose_wk<<<(Ff * Kd * KH + 255) / 256, 256>>>(Wkw);
    k_enc<<<(Ff * Kd * Bn + 255) / 256, 256>>>(zqst);

    // gx GEMM + fused passthrough copy
    k_gx<<<dim3(GXB + CPB, Gg / 128), 256>>>(zqst, bih,
        (const float2*)zex, (const float2*)zqx, (float2*)(out + 2));

    k_gru<<<Bn / 4, 768>>>(hidden, Whh, bhh);

    // predT[f][k][c] = sum_h WkT[f][h][k] * ctT[h][c] + Wk_b[f][k]
    k_gemm<<<dim3(Bn / 128, Kd / 64, Ff), 256>>>(p_wkT, p_ctT, p_predT,
        Kd, Bn, Bn, KH, (long)KH * Kd, 0L, (long)Kd * Bn, Wkb, Kd);
    // totals[f][b][c] = sum_k encT[f][k][b] * predT[f][k][c]
    k_gemm<<<dim3(Bn / 128, Bn / 64, Ff), 256>>>(p_encT, p_predT, p_totals,
        Bn, Bn, Bn, Kd, (long)Kd * Bn, (long)Kd * Bn, (long)Bn * Bn, nullptr, 0);

    k_lse<<<Ff * Bn, 128>>>();
    k_acc<<<Bn, 128>>>();
    k_final<<<1, 256>>>(out);
}